// round 1
// baseline (speedup 1.0000x reference)
#include <cuda_runtime.h>
#include <math.h>

#define SQ      8192
#define NBATCH  2
#define EMB     256
#define MH      8
#define DVC     32
#define S_TOT   21760
#define NQ      (NBATCH*SQ)      // 16384
#define NS      (NBATCH*S_TOT)   // 43520

// Scratch (device globals: no allocation allowed)
__device__ float g_vmask [(size_t)NS*256];   // (N,S,M*DV)
__device__ float g_logits[(size_t)NQ*128];   // (N,Q,M*16)
__device__ float g_deltas[(size_t)NQ*256];   // (N,Q,M*16*2)
__device__ float g_mdv   [(size_t)NQ*256];   // (N,Q,M*DV)

// ---------------------------------------------------------------------------
// Generic tiled SGEMM: C[Mr x Nc] = (A[Mr x 256] @ B[256 x Nc] + bias) * rowscale?
// BM=128, BN=64, BK=16, 256 threads, 8x4 register tile per thread.
// Grid: (Nc/64, Mr/128). All shapes divide exactly -> no bounds checks.
// ---------------------------------------------------------------------------
__global__ void __launch_bounds__(256) sgemm_kernel(
    const float* __restrict__ A, const float* __restrict__ B,
    const float* __restrict__ bias, const float* __restrict__ rowscale,
    float* __restrict__ C, int Nc)
{
    __shared__ float As[16][128];   // transposed: As[k][row]
    __shared__ float Bs[16][64];

    const int bm  = blockIdx.y * 128;
    const int bn  = blockIdx.x * 64;
    const int tid = threadIdx.x;
    const int tr  = tid >> 4;   // 0..15 -> rows tr*8..tr*8+7
    const int tc  = tid & 15;   // 0..15 -> cols tc*4..tc*4+3

    float acc[8][4];
    #pragma unroll
    for (int i = 0; i < 8; i++)
        #pragma unroll
        for (int j = 0; j < 4; j++) acc[i][j] = 0.f;

    for (int k0 = 0; k0 < 256; k0 += 16) {
        // Load A tile 128x16 (512 float4, 2 per thread), store transposed
        #pragma unroll
        for (int i = 0; i < 2; i++) {
            int idx = tid * 2 + i;          // 0..511
            int row = idx >> 2;             // 0..127
            int c4  = (idx & 3) << 2;       // 0,4,8,12
            float4 v = *(const float4*)&A[(size_t)(bm + row) * 256 + k0 + c4];
            As[c4 + 0][row] = v.x;
            As[c4 + 1][row] = v.y;
            As[c4 + 2][row] = v.z;
            As[c4 + 3][row] = v.w;
        }
        // Load B tile 16x64 (256 float4, 1 per thread)
        {
            int row = tid >> 4;             // 0..15
            int c4  = (tid & 15) << 2;      // 0..60
            *(float4*)&Bs[row][c4] =
                *(const float4*)&B[(size_t)(k0 + row) * Nc + bn + c4];
        }
        __syncthreads();

        #pragma unroll
        for (int k = 0; k < 16; k++) {
            float a[8], b[4];
            #pragma unroll
            for (int i = 0; i < 8; i++) a[i] = As[k][tr * 8 + i];
            #pragma unroll
            for (int j = 0; j < 4; j++) b[j] = Bs[k][tc * 4 + j];
            #pragma unroll
            for (int i = 0; i < 8; i++)
                #pragma unroll
                for (int j = 0; j < 4; j++)
                    acc[i][j] = fmaf(a[i], b[j], acc[i][j]);
        }
        __syncthreads();
    }

    #pragma unroll
    for (int i = 0; i < 8; i++) {
        int row = bm + tr * 8 + i;
        float rs = rowscale ? rowscale[row] : 1.f;
        #pragma unroll
        for (int j = 0; j < 4; j++) {
            int col = bn + tc * 4 + j;
            C[(size_t)row * Nc + col] = (acc[i][j] + bias[col]) * rs;
        }
    }
}

// ---------------------------------------------------------------------------
// Bilinear sampling + attention-weighted accumulation.
// One warp per (n,q,m); lane = dv channel (coalesced 128B gathers).
// Block = 256 threads = 8 warps = all M heads of one (n,q).
// ---------------------------------------------------------------------------
__device__ __forceinline__ float corner_val(const float* __restrict__ vl,
                                            int xi, int yi, int HW, float w)
{
    bool valid = (xi >= 0) & (xi < HW) & (yi >= 0) & (yi < HW);
    int xc = min(max(xi, 0), HW - 1);
    int yc = min(max(yi, 0), HW - 1);
    float v = valid ? __ldg(vl + (size_t)(yc * HW + xc) * 256) : 0.f;
    return w * v;
}

__global__ void __launch_bounds__(256) sample_kernel(
    const float* __restrict__ geom)    // (NQ, 4)
{
    const int m    = threadIdx.x >> 5;     // warp id = head
    const int lane = threadIdx.x & 31;     // dv channel
    const int nq   = blockIdx.x;           // 0..NQ-1
    const int n    = nq / SQ;

    // sigmoid geometry (all lanes redundant, broadcast loads)
    float cx = 1.f / (1.f + __expf(-geom[nq * 4 + 0]));
    float cy = 1.f / (1.f + __expf(-geom[nq * 4 + 1]));
    float sw = 0.125f / (1.f + __expf(-geom[nq * 4 + 2]));  // wh * (1/K) * SCALE
    float sh = 0.125f / (1.f + __expf(-geom[nq * 4 + 3]));

    // softmax over 16 attention logits for this head
    const float* lg = &g_logits[(size_t)nq * 128 + m * 16];
    float l[16], mx = -1e30f;
    #pragma unroll
    for (int p = 0; p < 16; p++) { l[p] = lg[p]; mx = fmaxf(mx, l[p]); }
    float s = 0.f;
    #pragma unroll
    for (int p = 0; p < 16; p++) { l[p] = __expf(l[p] - mx); s += l[p]; }
    const float inv = 1.f / s;

    const float* dl = &g_deltas[(size_t)nq * 256 + m * 32];
    const float* vbase = g_vmask + (size_t)n * S_TOT * 256 + m * 32 + lane;

    const int starts[4] = {0, 16384, 20480, 21504};

    float acc = 0.f;
    #pragma unroll
    for (int p = 0; p < 16; p++) {
        const int li = p >> 2;
        const int HW = 128 >> li;          // levels are square: 128,64,32,16
        const float a = l[p] * inv;

        float px = fmaf(dl[p * 2 + 0], sw, cx);
        float py = fmaf(dl[p * 2 + 1], sh, cy);
        float gx = fminf(fmaxf(2.f * px - 1.f, -1.f), 1.f);
        float gy = fminf(fmaxf(2.f * py - 1.f, -1.f), 1.f);
        float x = (gx + 1.f) * (HW * 0.5f) - 0.5f;
        float y = (gy + 1.f) * (HW * 0.5f) - 0.5f;
        float x0f = floorf(x), y0f = floorf(y);
        float wx = x - x0f, wy = y - y0f;
        int x0 = (int)x0f, y0 = (int)y0f;

        const float* vl = vbase + (size_t)starts[li] * 256;
        acc += corner_val(vl, x0,     y0,     HW, a * (1.f - wx) * (1.f - wy));
        acc += corner_val(vl, x0 + 1, y0,     HW, a * wx * (1.f - wy));
        acc += corner_val(vl, x0,     y0 + 1, HW, a * (1.f - wx) * wy);
        acc += corner_val(vl, x0 + 1, y0 + 1, HW, a * wx * wy);
    }
    g_mdv[(size_t)nq * 256 + m * 32 + lane] = acc;
}

// ---------------------------------------------------------------------------
// Launch
// Inputs (metadata order): queries, query_geometry_logits, value, value_mask,
//   W_off, b_off, W_attn, b_attn, W_val, b_val, W_out, b_out
// ---------------------------------------------------------------------------
static float* sym_addr(const void* sym)
{
    void* p = nullptr;
    cudaGetSymbolAddress(&p, sym);
    return (float*)p;
}

extern "C" void kernel_launch(void* const* d_in, const int* in_sizes, int n_in,
                              void* d_out, int out_size)
{
    const float* queries = (const float*)d_in[0];
    const float* geom    = (const float*)d_in[1];
    const float* value   = (const float*)d_in[2];
    const float* vmaskin = (const float*)d_in[3];
    const float* W_off   = (const float*)d_in[4];
    const float* b_off   = (const float*)d_in[5];
    const float* W_attn  = (const float*)d_in[6];
    const float* b_attn  = (const float*)d_in[7];
    const float* W_val   = (const float*)d_in[8];
    const float* b_val   = (const float*)d_in[9];
    const float* W_out   = (const float*)d_in[10];
    const float* b_out   = (const float*)d_in[11];
    float* out = (float*)d_out;

    float* vmask  = sym_addr(g_vmask);
    float* logits = sym_addr(g_logits);
    float* deltas = sym_addr(g_deltas);
    float* mdv    = sym_addr(g_mdv);

    // v_masked = mask * (value @ W_val + b_val)   [43520 x 256]
    sgemm_kernel<<<dim3(4, NS / 128), 256>>>(value, W_val, b_val, vmaskin, vmask, 256);
    // attn logits = queries @ W_attn + b_attn     [16384 x 128]
    sgemm_kernel<<<dim3(2, NQ / 128), 256>>>(queries, W_attn, b_attn, nullptr, logits, 128);
    // deltas = queries @ W_off + b_off            [16384 x 256]
    sgemm_kernel<<<dim3(4, NQ / 128), 256>>>(queries, W_off, b_off, nullptr, deltas, 256);
    // sampling + softmax + weighted sum           -> mdv [16384 x 256]
    sample_kernel<<<NQ, 256>>>(geom);
    // out = mdv @ W_out + b_out                   [16384 x 256]
    sgemm_kernel<<<dim3(4, NQ / 128), 256>>>(mdv, W_out, b_out, nullptr, out, 256);
}

// round 2
// speedup vs baseline: 1.4652x; 1.4652x over previous
#include <cuda_runtime.h>
#include <math.h>

#define SQ      8192
#define NBATCH  2
#define EMB     256
#define MH      8
#define DVC     32
#define S_TOT   21760
#define NQ      (NBATCH*SQ)      // 16384
#define NS      (NBATCH*S_TOT)   // 43520

// Scratch (device globals: no allocation allowed)
__device__ float g_vmask [(size_t)NS*256];   // (N,S,M*DV)
__device__ float g_logits[(size_t)NQ*128];   // (N,Q,M*16)
__device__ float g_deltas[(size_t)NQ*256];   // (N,Q,M*16*2)
__device__ float g_mdv   [(size_t)NQ*256];   // (N,Q,M*DV)

// ---------------------------------------------------------------------------
// f32x2 packed helpers (FFMA2 is PTX-only: fma.rn.f32x2)
// ---------------------------------------------------------------------------
__device__ __forceinline__ unsigned long long pack_dup(float v) {
    unsigned long long r;
    asm("mov.b64 %0, {%1, %1};" : "=l"(r) : "f"(v));
    return r;
}
__device__ __forceinline__ unsigned long long pack2(float lo, float hi) {
    unsigned long long r;
    asm("mov.b64 %0, {%1, %2};" : "=l"(r) : "f"(lo), "f"(hi));
    return r;
}
__device__ __forceinline__ float2 unpack2(unsigned long long v) {
    float2 r;
    asm("mov.b64 {%0, %1}, %2;" : "=f"(r.x), "=f"(r.y) : "l"(v));
    return r;
}
__device__ __forceinline__ void ffma2(unsigned long long& acc,
                                      unsigned long long a,
                                      unsigned long long b) {
    asm("fma.rn.f32x2 %0, %1, %2, %0;" : "+l"(acc) : "l"(a), "l"(b));
}

// ---------------------------------------------------------------------------
// Tiled SGEMM with packed f32x2 FMA:
// C[Mr x Nc] = (A[Mr x 256] @ B[256 x Nc] + bias) * rowscale?
// BM=128, BN=64, BK=16, 256 threads. Each thread: 8 rows (as 4 row-pairs) x 4 cols.
// ---------------------------------------------------------------------------
__global__ void __launch_bounds__(256) sgemm_kernel(
    const float* __restrict__ A, const float* __restrict__ B,
    const float* __restrict__ bias, const float* __restrict__ rowscale,
    float* __restrict__ C, int Nc)
{
    __shared__ float As[16][128];   // transposed: As[k][row]
    __shared__ float Bs[16][64];

    const int bm  = blockIdx.y * 128;
    const int bn  = blockIdx.x * 64;
    const int tid = threadIdx.x;
    const int tr  = tid >> 4;   // 0..15 -> rows tr*8..tr*8+7
    const int tc  = tid & 15;   // 0..15 -> cols tc*4..tc*4+3

    unsigned long long acc2[4][4];   // [row-pair][col], packed (row even, row odd)
    #pragma unroll
    for (int i = 0; i < 4; i++)
        #pragma unroll
        for (int j = 0; j < 4; j++) acc2[i][j] = 0ULL;

    for (int k0 = 0; k0 < 256; k0 += 16) {
        // Load A tile 128x16 (512 float4, 2 per thread), store transposed
        #pragma unroll
        for (int i = 0; i < 2; i++) {
            int idx = tid * 2 + i;          // 0..511
            int row = idx >> 2;             // 0..127
            int c4  = (idx & 3) << 2;       // 0,4,8,12
            float4 v = *(const float4*)&A[(size_t)(bm + row) * 256 + k0 + c4];
            As[c4 + 0][row] = v.x;
            As[c4 + 1][row] = v.y;
            As[c4 + 2][row] = v.z;
            As[c4 + 3][row] = v.w;
        }
        // Load B tile 16x64 (256 float4, 1 per thread)
        {
            int row = tid >> 4;             // 0..15
            int c4  = (tid & 15) << 2;      // 0..60
            *(float4*)&Bs[row][c4] =
                *(const float4*)&B[(size_t)(k0 + row) * Nc + bn + c4];
        }
        __syncthreads();

        #pragma unroll
        for (int k = 0; k < 16; k++) {
            unsigned long long aa[4], bb[4];
            #pragma unroll
            for (int i = 0; i < 4; i++) {
                float2 ap = *(const float2*)&As[k][tr * 8 + i * 2];
                aa[i] = pack2(ap.x, ap.y);
            }
            #pragma unroll
            for (int j = 0; j < 4; j++)
                bb[j] = pack_dup(Bs[k][tc * 4 + j]);
            #pragma unroll
            for (int i = 0; i < 4; i++)
                #pragma unroll
                for (int j = 0; j < 4; j++)
                    ffma2(acc2[i][j], aa[i], bb[j]);
        }
        __syncthreads();
    }

    const int colb = bn + tc * 4;
    float4 bv = *(const float4*)&bias[colb];
    #pragma unroll
    for (int i = 0; i < 4; i++) {
        int row0 = bm + tr * 8 + i * 2;
        float rs0 = rowscale ? rowscale[row0]     : 1.f;
        float rs1 = rowscale ? rowscale[row0 + 1] : 1.f;
        float2 c0 = unpack2(acc2[i][0]);
        float2 c1 = unpack2(acc2[i][1]);
        float2 c2 = unpack2(acc2[i][2]);
        float2 c3 = unpack2(acc2[i][3]);
        float4 lo = make_float4((c0.x + bv.x) * rs0, (c1.x + bv.y) * rs0,
                                (c2.x + bv.z) * rs0, (c3.x + bv.w) * rs0);
        float4 hi = make_float4((c0.y + bv.x) * rs1, (c1.y + bv.y) * rs1,
                                (c2.y + bv.z) * rs1, (c3.y + bv.w) * rs1);
        *(float4*)&C[(size_t)row0 * Nc + colb]       = lo;
        *(float4*)&C[(size_t)(row0 + 1) * Nc + colb] = hi;
    }
}

// ---------------------------------------------------------------------------
// Sampling, restructured:
// Phase 1 (threads 0..127): thread = (head m, point p). Computes softmax weight
//   (16-lane shfl reductions), geometry, bilinear corner weights (attn folded in)
//   and pre-scaled corner offsets. Invalid corners get weight 0 / offset 0.
//   Results packed to shared memory (int4 + float4 per point).
// Phase 2 (8 warps): warp m loops 16 points: 2 broadcast LDS.128 + 4 coalesced
//   128B gathers + 4 FFMA per point.
// ---------------------------------------------------------------------------
__global__ void __launch_bounds__(256) sample_kernel(
    const float* __restrict__ geom)    // (NQ, 4)
{
    __shared__ int4   sI[8][16];
    __shared__ float4 sW[8][16];

    const int nq = blockIdx.x;
    const int n  = nq / SQ;
    const int t  = threadIdx.x;

    if (t < 128) {
        const int m = t >> 4;
        const int p = t & 15;

        // geometry sigmoids (broadcast loads, cheap)
        float cx = 1.f / (1.f + __expf(-geom[nq * 4 + 0]));
        float cy = 1.f / (1.f + __expf(-geom[nq * 4 + 1]));
        float sw = 0.125f / (1.f + __expf(-geom[nq * 4 + 2]));
        float sh = 0.125f / (1.f + __expf(-geom[nq * 4 + 3]));

        // softmax over the 16 points of this head (16-lane segments)
        float l = g_logits[(size_t)nq * 128 + m * 16 + p];
        float mx = l;
        #pragma unroll
        for (int d = 8; d >= 1; d >>= 1)
            mx = fmaxf(mx, __shfl_xor_sync(0xffffffffu, mx, d, 16));
        float e = __expf(l - mx);
        float s = e;
        #pragma unroll
        for (int d = 8; d >= 1; d >>= 1)
            s += __shfl_xor_sync(0xffffffffu, s, d, 16);
        const float a = e / s;

        const float dx = g_deltas[(size_t)nq * 256 + m * 32 + 2 * p];
        const float dy = g_deltas[(size_t)nq * 256 + m * 32 + 2 * p + 1];

        const int li = p >> 2;
        const int HW = 128 >> li;
        const int starts[4] = {0, 16384, 20480, 21504};
        const int start = starts[li];

        float px = fmaf(dx, sw, cx);
        float py = fmaf(dy, sh, cy);
        float gx = fminf(fmaxf(2.f * px - 1.f, -1.f), 1.f);
        float gy = fminf(fmaxf(2.f * py - 1.f, -1.f), 1.f);
        float x = (gx + 1.f) * (HW * 0.5f) - 0.5f;
        float y = (gy + 1.f) * (HW * 0.5f) - 0.5f;
        float x0f = floorf(x), y0f = floorf(y);
        float wx = x - x0f, wy = y - y0f;
        int x0 = (int)x0f, y0 = (int)y0f;
        int x1 = x0 + 1,  y1 = y0 + 1;

        bool vx0 = (x0 >= 0) & (x0 < HW);
        bool vx1 = (x1 >= 0) & (x1 < HW);
        bool vy0 = (y0 >= 0) & (y0 < HW);
        bool vy1 = (y1 >= 0) & (y1 < HW);

        int4 idx;
        float4 w;
        idx.x = (vx0 & vy0) ? (start + y0 * HW + x0) * 256 : 0;
        idx.y = (vx1 & vy0) ? (start + y0 * HW + x1) * 256 : 0;
        idx.z = (vx0 & vy1) ? (start + y1 * HW + x0) * 256 : 0;
        idx.w = (vx1 & vy1) ? (start + y1 * HW + x1) * 256 : 0;
        w.x = (vx0 & vy0) ? a * (1.f - wx) * (1.f - wy) : 0.f;
        w.y = (vx1 & vy0) ? a * wx * (1.f - wy)         : 0.f;
        w.z = (vx0 & vy1) ? a * (1.f - wx) * wy         : 0.f;
        w.w = (vx1 & vy1) ? a * wx * wy                 : 0.f;

        sI[m][p] = idx;
        sW[m][p] = w;
    }
    __syncthreads();

    const int m    = t >> 5;
    const int lane = t & 31;
    const float* __restrict__ vbase =
        g_vmask + (size_t)n * S_TOT * 256 + m * 32 + lane;

    float acc = 0.f;
    #pragma unroll
    for (int p = 0; p < 16; p++) {
        int4   I = sI[m][p];
        float4 W = sW[m][p];
        acc = fmaf(W.x, __ldg(vbase + I.x), acc);
        acc = fmaf(W.y, __ldg(vbase + I.y), acc);
        acc = fmaf(W.z, __ldg(vbase + I.z), acc);
        acc = fmaf(W.w, __ldg(vbase + I.w), acc);
    }
    g_mdv[(size_t)nq * 256 + m * 32 + lane] = acc;
}

// ---------------------------------------------------------------------------
// Launch
// ---------------------------------------------------------------------------
static float* sym_addr(const void* sym)
{
    void* p = nullptr;
    cudaGetSymbolAddress(&p, sym);
    return (float*)p;
}

extern "C" void kernel_launch(void* const* d_in, const int* in_sizes, int n_in,
                              void* d_out, int out_size)
{
    const float* queries = (const float*)d_in[0];
    const float* geom    = (const float*)d_in[1];
    const float* value   = (const float*)d_in[2];
    const float* vmaskin = (const float*)d_in[3];
    const float* W_off   = (const float*)d_in[4];
    const float* b_off   = (const float*)d_in[5];
    const float* W_attn  = (const float*)d_in[6];
    const float* b_attn  = (const float*)d_in[7];
    const float* W_val   = (const float*)d_in[8];
    const float* b_val   = (const float*)d_in[9];
    const float* W_out   = (const float*)d_in[10];
    const float* b_out   = (const float*)d_in[11];
    float* out = (float*)d_out;

    float* vmask  = sym_addr(g_vmask);
    float* logits = sym_addr(g_logits);
    float* deltas = sym_addr(g_deltas);
    float* mdv    = sym_addr(g_mdv);

    // v_masked = mask * (value @ W_val + b_val)   [43520 x 256]
    sgemm_kernel<<<dim3(4, NS / 128), 256>>>(value, W_val, b_val, vmaskin, vmask, 256);
    // attn logits = queries @ W_attn + b_attn     [16384 x 128]
    sgemm_kernel<<<dim3(2, NQ / 128), 256>>>(queries, W_attn, b_attn, nullptr, logits, 128);
    // deltas = queries @ W_off + b_off            [16384 x 256]
    sgemm_kernel<<<dim3(4, NQ / 128), 256>>>(queries, W_off, b_off, nullptr, deltas, 256);
    // sampling + softmax + weighted sum           -> mdv [16384 x 256]
    sample_kernel<<<NQ, 256>>>(geom);
    // out = mdv @ W_out + b_out                   [16384 x 256]
    sgemm_kernel<<<dim3(4, NQ / 128), 256>>>(mdv, W_out, b_out, nullptr, out, 256);
}

// round 6
// speedup vs baseline: 1.9366x; 1.3218x over previous
#include <cuda_runtime.h>
#include <math.h>
#include <stdint.h>

#define SQ      8192
#define NBATCH  2
#define S_TOT   21760
#define NQ      (NBATCH*SQ)      // 16384
#define NS      (NBATCH*S_TOT)   // 43520

// Scratch (device globals: no allocation allowed)
__device__ float g_vmask [(size_t)NS*256];   // (N,S,M*DV)
__device__ float g_logits[(size_t)NQ*128];   // (N,Q,M*16)
__device__ float g_deltas[(size_t)NQ*256];   // (N,Q,M*16*2)
__device__ float g_mdv   [(size_t)NQ*256];   // (N,Q,M*DV)

// ===========================================================================
// tf32 helpers (mma.sync is baseline sm_80 PTX -> works on compute_103)
// ===========================================================================
__device__ __forceinline__ uint32_t f2tf32(float v) {
    uint32_t r;
    asm("cvt.rna.tf32.f32 %0, %1;" : "=r"(r) : "f"(v));
    return r;
}

__device__ __forceinline__ void mma_tf32(float c[4],
                                         uint32_t a0, uint32_t a1,
                                         uint32_t a2, uint32_t a3,
                                         uint32_t b0, uint32_t b1) {
    asm volatile(
        "mma.sync.aligned.m16n8k8.row.col.f32.tf32.tf32.f32 "
        "{%0,%1,%2,%3}, {%4,%5,%6,%7}, {%8,%9}, {%0,%1,%2,%3};"
        : "+f"(c[0]), "+f"(c[1]), "+f"(c[2]), "+f"(c[3])
        : "r"(a0), "r"(a1), "r"(a2), "r"(a3), "r"(b0), "r"(b1));
}

// ===========================================================================
// tf32 tensor-core GEMM via mma.sync (error-insensitive paths only):
//   C[Mr x Nc] = (A[Mr x 256] @ W[256 x Nc] + bias) (* rowscale)
// BM=128, BN=128, BK=16, 256 threads = 8 warps (4 x 2), warp tile 32x64.
// ===========================================================================
__global__ void __launch_bounds__(256) tf32mma_gemm(
    const float* __restrict__ A, const float* __restrict__ W,
    const float* __restrict__ bias, const float* __restrict__ rowscale,
    float* __restrict__ C, int Nc)
{
    __shared__ uint32_t As[16][136];   // [k][m] tf32 bits
    __shared__ uint32_t Bs[16][136];   // [k][n] tf32 bits

    const int tid  = threadIdx.x;
    const int wid  = tid >> 5;
    const int lane = tid & 31;
    const int wm   = wid & 3;
    const int wn   = wid >> 2;
    const int m0   = wm * 32;
    const int n0   = wn * 64;
    const int grp  = lane >> 2;        // 0..7
    const int q    = lane & 3;         // 0..3
    const int bm   = blockIdx.y * 128;
    const int bn   = blockIdx.x * 128;

    float c[2][8][4];
    #pragma unroll
    for (int i = 0; i < 2; i++)
        #pragma unroll
        for (int j = 0; j < 8; j++)
            #pragma unroll
            for (int e = 0; e < 4; e++) c[i][j][e] = 0.f;

    float4 ra[2], rb[2];
    #pragma unroll
    for (int i = 0; i < 2; i++) {
        int idx = tid * 2 + i;
        int arow = idx >> 2, akc = (idx & 3) << 2;
        int bkr  = idx >> 5, bnc = (idx & 31) << 2;
        ra[i] = *(const float4*)&A[(size_t)(bm + arow) * 256 + akc];
        rb[i] = *(const float4*)&W[(size_t)bkr * Nc + bn + bnc];
    }

    for (int k0 = 0; k0 < 256; k0 += 16) {
        #pragma unroll
        for (int i = 0; i < 2; i++) {
            int idx = tid * 2 + i;
            int arow = idx >> 2, akc = (idx & 3) << 2;
            As[akc + 0][arow] = f2tf32(ra[i].x);
            As[akc + 1][arow] = f2tf32(ra[i].y);
            As[akc + 2][arow] = f2tf32(ra[i].z);
            As[akc + 3][arow] = f2tf32(ra[i].w);
            int bkr = idx >> 5, bnc = (idx & 31) << 2;
            Bs[bkr][bnc + 0] = f2tf32(rb[i].x);
            Bs[bkr][bnc + 1] = f2tf32(rb[i].y);
            Bs[bkr][bnc + 2] = f2tf32(rb[i].z);
            Bs[bkr][bnc + 3] = f2tf32(rb[i].w);
        }
        __syncthreads();

        if (k0 + 16 < 256) {
            #pragma unroll
            for (int i = 0; i < 2; i++) {
                int idx = tid * 2 + i;
                int arow = idx >> 2, akc = (idx & 3) << 2;
                int bkr  = idx >> 5, bnc = (idx & 31) << 2;
                ra[i] = *(const float4*)&A[(size_t)(bm + arow) * 256 + k0 + 16 + akc];
                rb[i] = *(const float4*)&W[(size_t)(k0 + 16 + bkr) * Nc + bn + bnc];
            }
        }

        #pragma unroll
        for (int ks = 0; ks < 16; ks += 8) {
            uint32_t a[2][4];
            #pragma unroll
            for (int mf = 0; mf < 2; mf++) {
                int mr = m0 + mf * 16 + grp;
                a[mf][0] = As[ks + q][mr];
                a[mf][1] = As[ks + q][mr + 8];
                a[mf][2] = As[ks + q + 4][mr];
                a[mf][3] = As[ks + q + 4][mr + 8];
            }
            uint32_t b[8][2];
            #pragma unroll
            for (int nf = 0; nf < 8; nf++) {
                int nb = n0 + nf * 8 + grp;
                b[nf][0] = Bs[ks + q][nb];
                b[nf][1] = Bs[ks + q + 4][nb];
            }
            #pragma unroll
            for (int mf = 0; mf < 2; mf++)
                #pragma unroll
                for (int nf = 0; nf < 8; nf++)
                    mma_tf32(c[mf][nf], a[mf][0], a[mf][1], a[mf][2], a[mf][3],
                             b[nf][0], b[nf][1]);
        }
        __syncthreads();
    }

    #pragma unroll
    for (int mf = 0; mf < 2; mf++) {
        int r0 = bm + m0 + mf * 16 + grp;
        int r1 = r0 + 8;
        float rs0 = rowscale ? rowscale[r0] : 1.f;
        float rs1 = rowscale ? rowscale[r1] : 1.f;
        #pragma unroll
        for (int nf = 0; nf < 8; nf++) {
            int col = bn + n0 + nf * 8 + 2 * q;
            float2 bv = *(const float2*)&bias[col];
            float2 lo = make_float2((c[mf][nf][0] + bv.x) * rs0,
                                    (c[mf][nf][1] + bv.y) * rs0);
            float2 hi = make_float2((c[mf][nf][2] + bv.x) * rs1,
                                    (c[mf][nf][3] + bv.y) * rs1);
            *(float2*)&C[(size_t)r0 * Nc + col] = lo;
            *(float2*)&C[(size_t)r1 * Nc + col] = hi;
        }
    }
}

// ===========================================================================
// f32x2 packed helpers (FFMA2 is PTX-only: fma.rn.f32x2)
// ===========================================================================
__device__ __forceinline__ unsigned long long pack_dup(float v) {
    unsigned long long r;
    asm("mov.b64 %0, {%1, %1};" : "=l"(r) : "f"(v));
    return r;
}
__device__ __forceinline__ unsigned long long pack2(float lo, float hi) {
    unsigned long long r;
    asm("mov.b64 %0, {%1, %2};" : "=l"(r) : "f"(lo), "f"(hi));
    return r;
}
__device__ __forceinline__ float2 unpack2(unsigned long long v) {
    float2 r;
    asm("mov.b64 {%0, %1}, %2;" : "=f"(r.x), "=f"(r.y) : "l"(v));
    return r;
}
__device__ __forceinline__ void ffma2(unsigned long long& acc,
                                      unsigned long long a,
                                      unsigned long long b) {
    asm("fma.rn.f32x2 %0, %1, %2, %0;" : "+l"(acc) : "l"(a), "l"(b));
}

// ===========================================================================
// Exact fp32 tiled SGEMM (position-sensitive logits/deltas GEMMs)
// BM=128, BN=64, BK=16, 256 threads; 8 rows (4 pairs) x 4 cols per thread.
// ===========================================================================
__global__ void __launch_bounds__(256) sgemm_kernel(
    const float* __restrict__ A, const float* __restrict__ B,
    const float* __restrict__ bias, float* __restrict__ C, int Nc)
{
    __shared__ float As[16][128];
    __shared__ float Bs[16][64];

    const int bm  = blockIdx.y * 128;
    const int bn  = blockIdx.x * 64;
    const int tid = threadIdx.x;
    const int tr  = tid >> 4;
    const int tc  = tid & 15;

    unsigned long long acc2[4][4];
    #pragma unroll
    for (int i = 0; i < 4; i++)
        #pragma unroll
        for (int j = 0; j < 4; j++) acc2[i][j] = 0ULL;

    for (int k0 = 0; k0 < 256; k0 += 16) {
        #pragma unroll
        for (int i = 0; i < 2; i++) {
            int idx = tid * 2 + i;
            int row = idx >> 2;
            int c4  = (idx & 3) << 2;
            float4 v = *(const float4*)&A[(size_t)(bm + row) * 256 + k0 + c4];
            As[c4 + 0][row] = v.x;
            As[c4 + 1][row] = v.y;
            As[c4 + 2][row] = v.z;
            As[c4 + 3][row] = v.w;
        }
        {
            int row = tid >> 4;
            int c4  = (tid & 15) << 2;
            *(float4*)&Bs[row][c4] =
                *(const float4*)&B[(size_t)(k0 + row) * Nc + bn + c4];
        }
        __syncthreads();

        #pragma unroll
        for (int k = 0; k < 16; k++) {
            unsigned long long aa[4], bb[4];
            #pragma unroll
            for (int i = 0; i < 4; i++) {
                float2 ap = *(const float2*)&As[k][tr * 8 + i * 2];
                aa[i] = pack2(ap.x, ap.y);
            }
            #pragma unroll
            for (int j = 0; j < 4; j++)
                bb[j] = pack_dup(Bs[k][tc * 4 + j]);
            #pragma unroll
            for (int i = 0; i < 4; i++)
                #pragma unroll
                for (int j = 0; j < 4; j++)
                    ffma2(acc2[i][j], aa[i], bb[j]);
        }
        __syncthreads();
    }

    const int colb = bn + tc * 4;
    float4 bv = *(const float4*)&bias[colb];
    #pragma unroll
    for (int i = 0; i < 4; i++) {
        int row0 = bm + tr * 8 + i * 2;
        float2 c0 = unpack2(acc2[i][0]);
        float2 c1 = unpack2(acc2[i][1]);
        float2 c2 = unpack2(acc2[i][2]);
        float2 c3 = unpack2(acc2[i][3]);
        float4 lo = make_float4(c0.x + bv.x, c1.x + bv.y, c2.x + bv.z, c3.x + bv.w);
        float4 hi = make_float4(c0.y + bv.x, c1.y + bv.y, c2.y + bv.z, c3.y + bv.w);
        *(float4*)&C[(size_t)row0 * Nc + colb]       = lo;
        *(float4*)&C[(size_t)(row0 + 1) * Nc + colb] = hi;
    }
}

// ===========================================================================
// Sampling: phase 1 precomputes per-point weights/offsets; phase 2 gathers
// with 16-wide load batching and 4 accumulators for MLP.
// ===========================================================================
__global__ void __launch_bounds__(256) sample_kernel(
    const float* __restrict__ geom)
{
    __shared__ int4   sI[8][16];
    __shared__ float4 sW[8][16];

    const int nq = blockIdx.x;
    const int n  = nq / SQ;
    const int t  = threadIdx.x;

    if (t < 128) {
        const int m = t >> 4;
        const int p = t & 15;

        float cx = 1.f / (1.f + __expf(-geom[nq * 4 + 0]));
        float cy = 1.f / (1.f + __expf(-geom[nq * 4 + 1]));
        float sw = 0.125f / (1.f + __expf(-geom[nq * 4 + 2]));
        float sh = 0.125f / (1.f + __expf(-geom[nq * 4 + 3]));

        float l = g_logits[(size_t)nq * 128 + m * 16 + p];
        float mx = l;
        #pragma unroll
        for (int d = 8; d >= 1; d >>= 1)
            mx = fmaxf(mx, __shfl_xor_sync(0xffffffffu, mx, d, 16));
        float e = __expf(l - mx);
        float s = e;
        #pragma unroll
        for (int d = 8; d >= 1; d >>= 1)
            s += __shfl_xor_sync(0xffffffffu, s, d, 16);
        const float a = e / s;

        const float dx = g_deltas[(size_t)nq * 256 + m * 32 + 2 * p];
        const float dy = g_deltas[(size_t)nq * 256 + m * 32 + 2 * p + 1];

        const int li = p >> 2;
        const int HW = 128 >> li;
        const int starts[4] = {0, 16384, 20480, 21504};
        const int start = starts[li];

        float px = fmaf(dx, sw, cx);
        float py = fmaf(dy, sh, cy);
        float gx = fminf(fmaxf(2.f * px - 1.f, -1.f), 1.f);
        float gy = fminf(fmaxf(2.f * py - 1.f, -1.f), 1.f);
        float x = (gx + 1.f) * (HW * 0.5f) - 0.5f;
        float y = (gy + 1.f) * (HW * 0.5f) - 0.5f;
        float x0f = floorf(x), y0f = floorf(y);
        float wx = x - x0f, wy = y - y0f;
        int x0 = (int)x0f, y0 = (int)y0f;
        int x1 = x0 + 1,  y1 = y0 + 1;

        bool vx0 = (x0 >= 0) & (x0 < HW);
        bool vx1 = (x1 >= 0) & (x1 < HW);
        bool vy0 = (y0 >= 0) & (y0 < HW);
        bool vy1 = (y1 >= 0) & (y1 < HW);

        int4 idx;
        float4 w;
        idx.x = (vx0 & vy0) ? (start + y0 * HW + x0) * 256 : 0;
        idx.y = (vx1 & vy0) ? (start + y0 * HW + x1) * 256 : 0;
        idx.z = (vx0 & vy1) ? (start + y1 * HW + x0) * 256 : 0;
        idx.w = (vx1 & vy1) ? (start + y1 * HW + x1) * 256 : 0;
        w.x = (vx0 & vy0) ? a * (1.f - wx) * (1.f - wy) : 0.f;
        w.y = (vx1 & vy0) ? a * wx * (1.f - wy)         : 0.f;
        w.z = (vx0 & vy1) ? a * (1.f - wx) * wy         : 0.f;
        w.w = (vx1 & vy1) ? a * wx * wy                 : 0.f;

        sI[m][p] = idx;
        sW[m][p] = w;
    }
    __syncthreads();

    const int m    = t >> 5;
    const int lane = t & 31;
    const float* __restrict__ vbase =
        g_vmask + (size_t)n * S_TOT * 256 + m * 32 + lane;

    float acc0 = 0.f, acc1 = 0.f, acc2 = 0.f, acc3 = 0.f;
    #pragma unroll
    for (int g = 0; g < 4; g++) {
        int4   Ia = sI[m][4*g+0], Ib = sI[m][4*g+1], Ic = sI[m][4*g+2], Id = sI[m][4*g+3];
        float4 Wa = sW[m][4*g+0], Wb = sW[m][4*g+1], Wc = sW[m][4*g+2], Wd = sW[m][4*g+3];
        float va0 = __ldg(vbase + Ia.x), va1 = __ldg(vbase + Ia.y);
        float va2 = __ldg(vbase + Ia.z), va3 = __ldg(vbase + Ia.w);
        float vb0 = __ldg(vbase + Ib.x), vb1 = __ldg(vbase + Ib.y);
        float vb2 = __ldg(vbase + Ib.z), vb3 = __ldg(vbase + Ib.w);
        float vc0 = __ldg(vbase + Ic.x), vc1 = __ldg(vbase + Ic.y);
        float vc2 = __ldg(vbase + Ic.z), vc3 = __ldg(vbase + Ic.w);
        float vd0 = __ldg(vbase + Id.x), vd1 = __ldg(vbase + Id.y);
        float vd2 = __ldg(vbase + Id.z), vd3 = __ldg(vbase + Id.w);
        acc0 = fmaf(Wa.x, va0, acc0); acc0 = fmaf(Wa.y, va1, acc0);
        acc0 = fmaf(Wa.z, va2, acc0); acc0 = fmaf(Wa.w, va3, acc0);
        acc1 = fmaf(Wb.x, vb0, acc1); acc1 = fmaf(Wb.y, vb1, acc1);
        acc1 = fmaf(Wb.z, vb2, acc1); acc1 = fmaf(Wb.w, vb3, acc1);
        acc2 = fmaf(Wc.x, vc0, acc2); acc2 = fmaf(Wc.y, vc1, acc2);
        acc2 = fmaf(Wc.z, vc2, acc2); acc2 = fmaf(Wc.w, vc3, acc2);
        acc3 = fmaf(Wd.x, vd0, acc3); acc3 = fmaf(Wd.y, vd1, acc3);
        acc3 = fmaf(Wd.z, vd2, acc3); acc3 = fmaf(Wd.w, vd3, acc3);
    }
    g_mdv[(size_t)nq * 256 + m * 32 + lane] = (acc0 + acc1) + (acc2 + acc3);
}

// ===========================================================================
// Launch
// ===========================================================================
static float* sym_addr(const void* sym)
{
    void* p = nullptr;
    cudaGetSymbolAddress(&p, sym);
    return (float*)p;
}

extern "C" void kernel_launch(void* const* d_in, const int* in_sizes, int n_in,
                              void* d_out, int out_size)
{
    const float* queries = (const float*)d_in[0];
    const float* geom    = (const float*)d_in[1];
    const float* value   = (const float*)d_in[2];
    const float* vmaskin = (const float*)d_in[3];
    const float* W_off   = (const float*)d_in[4];
    const float* b_off   = (const float*)d_in[5];
    const float* W_attn  = (const float*)d_in[6];
    const float* b_attn  = (const float*)d_in[7];
    const float* W_val   = (const float*)d_in[8];
    const float* b_val   = (const float*)d_in[9];
    const float* W_out   = (const float*)d_in[10];
    const float* b_out   = (const float*)d_in[11];
    float* out = (float*)d_out;

    float* vmask  = sym_addr(g_vmask);
    float* logits = sym_addr(g_logits);
    float* deltas = sym_addr(g_deltas);
    float* mdv    = sym_addr(g_mdv);

    // v_masked = mask * (value @ W_val + b_val)   [43520 x 256]  (tf32 MMA)
    tf32mma_gemm<<<dim3(2, NS / 128), 256>>>(value, W_val, b_val, vmaskin, vmask, 256);
    // attn logits = queries @ W_attn + b_attn     [16384 x 128]  (fp32 exact)
    sgemm_kernel<<<dim3(2, NQ / 128), 256>>>(queries, W_attn, b_attn, logits, 128);
    // deltas = queries @ W_off + b_off            [16384 x 256]  (fp32 exact)
    sgemm_kernel<<<dim3(4, NQ / 128), 256>>>(queries, W_off, b_off, deltas, 256);
    // sampling + softmax + weighted sum           -> mdv [16384 x 256]
    sample_kernel<<<NQ, 256>>>(geom);
    // out = mdv @ W_out + b_out                   [16384 x 256]  (tf32 MMA)
    tf32mma_gemm<<<dim3(2, NQ / 128), 256>>>(mdv, W_out, b_out, nullptr, out, 256);
}

// round 7
// speedup vs baseline: 2.2532x; 1.1634x over previous
#include <cuda_runtime.h>
#include <math.h>
#include <stdint.h>

#define SQ      8192
#define NBATCH  2
#define S_TOT   21760
#define NQ      (NBATCH*SQ)      // 16384
#define NS      (NBATCH*S_TOT)   // 43520

// Fused phase-1 grid: 680 tf32-vmask CTAs + 256 logits CTAs + 512 deltas CTAs
#define N_VM   680
#define N_LG   256
#define N_DL   512
#define N_TOT  1448              // = 8 * 181; 997 is prime & coprime

// Scratch (device globals: no allocation allowed)
__device__ float g_vmask [(size_t)NS*256];   // (N,S,M*DV)
__device__ float g_logits[(size_t)NQ*128];   // (N,Q,M*16)
__device__ float g_deltas[(size_t)NQ*256];   // (N,Q,M*16*2)
__device__ float g_mdv   [(size_t)NQ*256];   // (N,Q,M*DV)

// ===========================================================================
// tf32 helpers (mma.sync is baseline sm_80 PTX -> works on compute_103)
// ===========================================================================
__device__ __forceinline__ uint32_t f2tf32(float v) {
    uint32_t r;
    asm("cvt.rna.tf32.f32 %0, %1;" : "=r"(r) : "f"(v));
    return r;
}

__device__ __forceinline__ void mma_tf32(float c[4],
                                         uint32_t a0, uint32_t a1,
                                         uint32_t a2, uint32_t a3,
                                         uint32_t b0, uint32_t b1) {
    asm volatile(
        "mma.sync.aligned.m16n8k8.row.col.f32.tf32.tf32.f32 "
        "{%0,%1,%2,%3}, {%4,%5,%6,%7}, {%8,%9}, {%0,%1,%2,%3};"
        : "+f"(c[0]), "+f"(c[1]), "+f"(c[2]), "+f"(c[3])
        : "r"(a0), "r"(a1), "r"(a2), "r"(a3), "r"(b0), "r"(b1));
}

// ===========================================================================
// tf32 tensor-core GEMM body (error-insensitive paths only):
//   C[.. x Nc] = (A[.. x 256] @ W[256 x Nc] + bias) (* rowscale)
// Tile 128x128, BK=16, 256 threads = 8 warps (4 x 2), warp tile 32x64.
// ===========================================================================
__device__ void tf32_gemm_body(
    int bx, int by,
    const float* __restrict__ A, const float* __restrict__ W,
    const float* __restrict__ bias, const float* __restrict__ rowscale,
    float* __restrict__ C, int Nc)
{
    __shared__ uint32_t As[16][136];   // [k][m] tf32 bits
    __shared__ uint32_t Bs[16][136];   // [k][n] tf32 bits

    const int tid  = threadIdx.x;
    const int wid  = tid >> 5;
    const int lane = tid & 31;
    const int m0   = (wid & 3) * 32;
    const int n0   = (wid >> 2) * 64;
    const int grp  = lane >> 2;        // 0..7
    const int q    = lane & 3;         // 0..3
    const int bm   = by * 128;
    const int bn   = bx * 128;

    float c[2][8][4];
    #pragma unroll
    for (int i = 0; i < 2; i++)
        #pragma unroll
        for (int j = 0; j < 8; j++)
            #pragma unroll
            for (int e = 0; e < 4; e++) c[i][j][e] = 0.f;

    float4 ra[2], rb[2];
    #pragma unroll
    for (int i = 0; i < 2; i++) {
        int idx = tid * 2 + i;
        int arow = idx >> 2, akc = (idx & 3) << 2;
        int bkr  = idx >> 5, bnc = (idx & 31) << 2;
        ra[i] = *(const float4*)&A[(size_t)(bm + arow) * 256 + akc];
        rb[i] = *(const float4*)&W[(size_t)bkr * Nc + bn + bnc];
    }

    for (int k0 = 0; k0 < 256; k0 += 16) {
        #pragma unroll
        for (int i = 0; i < 2; i++) {
            int idx = tid * 2 + i;
            int arow = idx >> 2, akc = (idx & 3) << 2;
            As[akc + 0][arow] = f2tf32(ra[i].x);
            As[akc + 1][arow] = f2tf32(ra[i].y);
            As[akc + 2][arow] = f2tf32(ra[i].z);
            As[akc + 3][arow] = f2tf32(ra[i].w);
            int bkr = idx >> 5, bnc = (idx & 31) << 2;
            Bs[bkr][bnc + 0] = f2tf32(rb[i].x);
            Bs[bkr][bnc + 1] = f2tf32(rb[i].y);
            Bs[bkr][bnc + 2] = f2tf32(rb[i].z);
            Bs[bkr][bnc + 3] = f2tf32(rb[i].w);
        }
        __syncthreads();

        if (k0 + 16 < 256) {
            #pragma unroll
            for (int i = 0; i < 2; i++) {
                int idx = tid * 2 + i;
                int arow = idx >> 2, akc = (idx & 3) << 2;
                int bkr  = idx >> 5, bnc = (idx & 31) << 2;
                ra[i] = *(const float4*)&A[(size_t)(bm + arow) * 256 + k0 + 16 + akc];
                rb[i] = *(const float4*)&W[(size_t)(k0 + 16 + bkr) * Nc + bn + bnc];
            }
        }

        #pragma unroll
        for (int ks = 0; ks < 16; ks += 8) {
            uint32_t a[2][4];
            #pragma unroll
            for (int mf = 0; mf < 2; mf++) {
                int mr = m0 + mf * 16 + grp;
                a[mf][0] = As[ks + q][mr];
                a[mf][1] = As[ks + q][mr + 8];
                a[mf][2] = As[ks + q + 4][mr];
                a[mf][3] = As[ks + q + 4][mr + 8];
            }
            uint32_t b[8][2];
            #pragma unroll
            for (int nf = 0; nf < 8; nf++) {
                int nb = n0 + nf * 8 + grp;
                b[nf][0] = Bs[ks + q][nb];
                b[nf][1] = Bs[ks + q + 4][nb];
            }
            #pragma unroll
            for (int mf = 0; mf < 2; mf++)
                #pragma unroll
                for (int nf = 0; nf < 8; nf++)
                    mma_tf32(c[mf][nf], a[mf][0], a[mf][1], a[mf][2], a[mf][3],
                             b[nf][0], b[nf][1]);
        }
        __syncthreads();
    }

    #pragma unroll
    for (int mf = 0; mf < 2; mf++) {
        int r0 = bm + m0 + mf * 16 + grp;
        int r1 = r0 + 8;
        float rs0 = rowscale ? rowscale[r0] : 1.f;
        float rs1 = rowscale ? rowscale[r1] : 1.f;
        #pragma unroll
        for (int nf = 0; nf < 8; nf++) {
            int col = bn + n0 + nf * 8 + 2 * q;
            float2 bv = *(const float2*)&bias[col];
            float2 lo = make_float2((c[mf][nf][0] + bv.x) * rs0,
                                    (c[mf][nf][1] + bv.y) * rs0);
            float2 hi = make_float2((c[mf][nf][2] + bv.x) * rs1,
                                    (c[mf][nf][3] + bv.y) * rs1);
            *(float2*)&C[(size_t)r0 * Nc + col] = lo;
            *(float2*)&C[(size_t)r1 * Nc + col] = hi;
        }
    }
}

// ===========================================================================
// f32x2 packed helpers (FFMA2 is PTX-only: fma.rn.f32x2)
// ===========================================================================
__device__ __forceinline__ unsigned long long pack_dup(float v) {
    unsigned long long r;
    asm("mov.b64 %0, {%1, %1};" : "=l"(r) : "f"(v));
    return r;
}
__device__ __forceinline__ unsigned long long pack2(float lo, float hi) {
    unsigned long long r;
    asm("mov.b64 %0, {%1, %2};" : "=l"(r) : "f"(lo), "f"(hi));
    return r;
}
__device__ __forceinline__ float2 unpack2(unsigned long long v) {
    float2 r;
    asm("mov.b64 {%0, %1}, %2;" : "=f"(r.x), "=f"(r.y) : "l"(v));
    return r;
}
__device__ __forceinline__ void ffma2(unsigned long long& acc,
                                      unsigned long long a,
                                      unsigned long long b) {
    asm("fma.rn.f32x2 %0, %1, %2, %0;" : "+l"(acc) : "l"(a), "l"(b));
}

// ===========================================================================
// Exact fp32 SGEMM body (position-sensitive logits/deltas)
// BM=128, BN=64, BK=16, 256 threads; 8 rows (4 pairs) x 4 cols per thread.
// ===========================================================================
__device__ void sgemm_body(
    int bx, int by,
    const float* __restrict__ A, const float* __restrict__ B,
    const float* __restrict__ bias, float* __restrict__ C, int Nc)
{
    __shared__ float Asf[16][128];
    __shared__ float Bsf[16][64];

    const int bm  = by * 128;
    const int bn  = bx * 64;
    const int tid = threadIdx.x;
    const int tr  = tid >> 4;
    const int tc  = tid & 15;

    unsigned long long acc2[4][4];
    #pragma unroll
    for (int i = 0; i < 4; i++)
        #pragma unroll
        for (int j = 0; j < 4; j++) acc2[i][j] = 0ULL;

    for (int k0 = 0; k0 < 256; k0 += 16) {
        #pragma unroll
        for (int i = 0; i < 2; i++) {
            int idx = tid * 2 + i;
            int row = idx >> 2;
            int c4  = (idx & 3) << 2;
            float4 v = *(const float4*)&A[(size_t)(bm + row) * 256 + k0 + c4];
            Asf[c4 + 0][row] = v.x;
            Asf[c4 + 1][row] = v.y;
            Asf[c4 + 2][row] = v.z;
            Asf[c4 + 3][row] = v.w;
        }
        {
            int row = tid >> 4;
            int c4  = (tid & 15) << 2;
            *(float4*)&Bsf[row][c4] =
                *(const float4*)&B[(size_t)(k0 + row) * Nc + bn + c4];
        }
        __syncthreads();

        #pragma unroll
        for (int k = 0; k < 16; k++) {
            unsigned long long aa[4], bb[4];
            #pragma unroll
            for (int i = 0; i < 4; i++) {
                float2 ap = *(const float2*)&Asf[k][tr * 8 + i * 2];
                aa[i] = pack2(ap.x, ap.y);
            }
            #pragma unroll
            for (int j = 0; j < 4; j++)
                bb[j] = pack_dup(Bsf[k][tc * 4 + j]);
            #pragma unroll
            for (int i = 0; i < 4; i++)
                #pragma unroll
                for (int j = 0; j < 4; j++)
                    ffma2(acc2[i][j], aa[i], bb[j]);
        }
        __syncthreads();
    }

    const int colb = bn + tc * 4;
    float4 bv = *(const float4*)&bias[colb];
    #pragma unroll
    for (int i = 0; i < 4; i++) {
        int row0 = bm + tr * 8 + i * 2;
        float2 c0 = unpack2(acc2[i][0]);
        float2 c1 = unpack2(acc2[i][1]);
        float2 c2 = unpack2(acc2[i][2]);
        float2 c3 = unpack2(acc2[i][3]);
        float4 lo = make_float4(c0.x + bv.x, c1.x + bv.y, c2.x + bv.z, c3.x + bv.w);
        float4 hi = make_float4(c0.y + bv.x, c1.y + bv.y, c2.y + bv.z, c3.y + bv.w);
        *(float4*)&C[(size_t)row0 * Nc + colb]       = lo;
        *(float4*)&C[(size_t)(row0 + 1) * Nc + colb] = hi;
    }
}

// ===========================================================================
// Fused phase-1: heterogeneous CTAs (tensor-pipe vmask GEMM runs concurrently
// with fma-pipe logits/deltas GEMMs). Block role from permuted block id.
// ===========================================================================
__global__ void __launch_bounds__(256) phase1_kernel(
    const float* __restrict__ value,   const float* __restrict__ W_val,
    const float* __restrict__ b_val,   const float* __restrict__ vmaskin,
    const float* __restrict__ queries, const float* __restrict__ W_attn,
    const float* __restrict__ b_attn,  const float* __restrict__ W_off,
    const float* __restrict__ b_off)
{
    int sid = (int)(((long long)blockIdx.x * 997) % N_TOT);
    if (sid < N_VM) {
        tf32_gemm_body(sid & 1, sid >> 1, value, W_val, b_val, vmaskin,
                       g_vmask, 256);
    } else if (sid < N_VM + N_LG) {
        int t = sid - N_VM;
        sgemm_body(t & 1, t >> 1, queries, W_attn, b_attn, g_logits, 128);
    } else {
        int t = sid - N_VM - N_LG;
        sgemm_body(t & 3, t >> 2, queries, W_off, b_off, g_deltas, 256);
    }
}

// ===========================================================================
// Output projection: standalone tf32 GEMM
// ===========================================================================
__global__ void __launch_bounds__(256) outproj_kernel(
    const float* __restrict__ bias, const float* __restrict__ W,
    float* __restrict__ out)
{
    tf32_gemm_body(blockIdx.x, blockIdx.y, g_mdv, W, bias, nullptr, out, 256);
}

// ===========================================================================
// Sampling.
// Phase 1 (threads 0..127): per-(head,point) softmax/geometry/bilinear ->
//   packed corner offsets + attn-folded weights in smem.
// Phase 2 (8 warps, warp=head): lane = (corner = lane>>3, chanblk = lane&7).
//   ONE LDG.128 per point per lane covers all 4 corners x 4 channels.
//   Corner partials merged once at the end via shfl_xor butterfly.
// ===========================================================================
__global__ void __launch_bounds__(256) sample_kernel(
    const float* __restrict__ geom)
{
    __shared__ int4   sI[8][16];
    __shared__ float4 sW[8][16];

    const int nq = blockIdx.x;
    const int n  = nq / SQ;
    const int t  = threadIdx.x;

    if (t < 128) {
        const int m = t >> 4;
        const int p = t & 15;

        float cx = 1.f / (1.f + __expf(-geom[nq * 4 + 0]));
        float cy = 1.f / (1.f + __expf(-geom[nq * 4 + 1]));
        float sw = 0.125f / (1.f + __expf(-geom[nq * 4 + 2]));
        float sh = 0.125f / (1.f + __expf(-geom[nq * 4 + 3]));

        float l = g_logits[(size_t)nq * 128 + m * 16 + p];
        float mx = l;
        #pragma unroll
        for (int d = 8; d >= 1; d >>= 1)
            mx = fmaxf(mx, __shfl_xor_sync(0xffffffffu, mx, d, 16));
        float e = __expf(l - mx);
        float s = e;
        #pragma unroll
        for (int d = 8; d >= 1; d >>= 1)
            s += __shfl_xor_sync(0xffffffffu, s, d, 16);
        const float a = e / s;

        const float dx = g_deltas[(size_t)nq * 256 + m * 32 + 2 * p];
        const float dy = g_deltas[(size_t)nq * 256 + m * 32 + 2 * p + 1];

        const int li = p >> 2;
        const int HW = 128 >> li;
        const int starts[4] = {0, 16384, 20480, 21504};
        const int start = starts[li];

        float px = fmaf(dx, sw, cx);
        float py = fmaf(dy, sh, cy);
        float gx = fminf(fmaxf(2.f * px - 1.f, -1.f), 1.f);
        float gy = fminf(fmaxf(2.f * py - 1.f, -1.f), 1.f);
        float x = (gx + 1.f) * (HW * 0.5f) - 0.5f;
        float y = (gy + 1.f) * (HW * 0.5f) - 0.5f;
        float x0f = floorf(x), y0f = floorf(y);
        float wx = x - x0f, wy = y - y0f;
        int x0 = (int)x0f, y0 = (int)y0f;
        int x1 = x0 + 1,  y1 = y0 + 1;

        bool vx0 = (x0 >= 0) & (x0 < HW);
        bool vx1 = (x1 >= 0) & (x1 < HW);
        bool vy0 = (y0 >= 0) & (y0 < HW);
        bool vy1 = (y1 >= 0) & (y1 < HW);

        int4 idx;
        float4 w;
        idx.x = (vx0 & vy0) ? (start + y0 * HW + x0) * 256 : 0;
        idx.y = (vx1 & vy0) ? (start + y0 * HW + x1) * 256 : 0;
        idx.z = (vx0 & vy1) ? (start + y1 * HW + x0) * 256 : 0;
        idx.w = (vx1 & vy1) ? (start + y1 * HW + x1) * 256 : 0;
        w.x = (vx0 & vy0) ? a * (1.f - wx) * (1.f - wy) : 0.f;
        w.y = (vx1 & vy0) ? a * wx * (1.f - wy)         : 0.f;
        w.z = (vx0 & vy1) ? a * (1.f - wx) * wy         : 0.f;
        w.w = (vx1 & vy1) ? a * wx * wy                 : 0.f;

        sI[m][p] = idx;
        sW[m][p] = w;
    }
    __syncthreads();

    const int m      = t >> 5;
    const int lane   = t & 31;
    const int corner = lane >> 3;      // 0..3
    const int cb     = lane & 7;       // channel block (4 channels)
    const float* __restrict__ vb4 =
        g_vmask + (size_t)n * S_TOT * 256 + m * 32 + cb * 4;
    const int*   __restrict__ pI = (const int*)&sI[m][0]   + corner;
    const float* __restrict__ pW = (const float*)&sW[m][0] + corner;

    float4 acc = make_float4(0.f, 0.f, 0.f, 0.f);
    #pragma unroll
    for (int p = 0; p < 16; p++) {
        int   I = pI[4 * p];
        float w = pW[4 * p];
        float4 v = *(const float4*)(vb4 + I);
        acc.x = fmaf(w, v.x, acc.x);
        acc.y = fmaf(w, v.y, acc.y);
        acc.z = fmaf(w, v.z, acc.z);
        acc.w = fmaf(w, v.w, acc.w);
    }

    // merge the 4 corner groups (lanes differing in bits 3,4 of lane id)
    #pragma unroll
    for (int d = 8; d <= 16; d <<= 1) {
        acc.x += __shfl_xor_sync(0xffffffffu, acc.x, d);
        acc.y += __shfl_xor_sync(0xffffffffu, acc.y, d);
        acc.z += __shfl_xor_sync(0xffffffffu, acc.z, d);
        acc.w += __shfl_xor_sync(0xffffffffu, acc.w, d);
    }
    if (lane < 8)
        *(float4*)&g_mdv[(size_t)nq * 256 + m * 32 + cb * 4] = acc;
}

// ===========================================================================
// Launch
// ===========================================================================
extern "C" void kernel_launch(void* const* d_in, const int* in_sizes, int n_in,
                              void* d_out, int out_size)
{
    const float* queries = (const float*)d_in[0];
    const float* geom    = (const float*)d_in[1];
    const float* value   = (const float*)d_in[2];
    const float* vmaskin = (const float*)d_in[3];
    const float* W_off   = (const float*)d_in[4];
    const float* b_off   = (const float*)d_in[5];
    const float* W_attn  = (const float*)d_in[6];
    const float* b_attn  = (const float*)d_in[7];
    const float* W_val   = (const float*)d_in[8];
    const float* b_val   = (const float*)d_in[9];
    const float* W_out   = (const float*)d_in[10];
    const float* b_out   = (const float*)d_in[11];
    float* out = (float*)d_out;

    // Phase 1 (concurrent): vmask tf32-MMA + logits/deltas exact fp32
    phase1_kernel<<<N_TOT, 256>>>(value, W_val, b_val, vmaskin,
                                  queries, W_attn, b_attn, W_off, b_off);
    // Phase 2: sampling + softmax + weighted sum -> g_mdv
    sample_kernel<<<NQ, 256>>>(geom);
    // Phase 3: out = mdv @ W_out + b_out (tf32 MMA)
    outproj_kernel<<<dim3(2, NQ / 128), 256>>>(b_out, W_out, out);
}

// round 9
// speedup vs baseline: 2.3357x; 1.0366x over previous
#include <cuda_runtime.h>
#include <math.h>
#include <stdint.h>

#define SQ      8192
#define NBATCH  2
#define S_TOT   21760
#define NQ      (NBATCH*SQ)      // 16384
#define NS      (NBATCH*S_TOT)   // 43520

// Fused phase-1 grid: 680 tf32-vmask CTAs + 256 logits CTAs + 512 deltas CTAs
#define N_VM   680
#define N_LG   256
#define N_DL   512
#define N_TOT  1448

// tf32 pipeline smem geometry
#define A_STAGE_BYTES  (128*20*4)              // [m][20] stride-20 pad
#define B_STAGE_BYTES  (16*136*4)              // [k][136]
#define STAGE_BYTES    (A_STAGE_BYTES + B_STAGE_BYTES)   // 18944
#define TF32_DSMEM     (3 * STAGE_BYTES)                 // 56832

// Scratch (device globals: no allocation allowed)
__device__ float g_vmask [(size_t)NS*256];
__device__ float g_logits[(size_t)NQ*128];
__device__ float g_deltas[(size_t)NQ*256];
__device__ float g_mdv   [(size_t)NQ*256];
__device__ float g_Wval_r[256*256];   // tf32-RNA pre-rounded weights
__device__ float g_Wout_r[256*256];

// ===========================================================================
// PTX helpers
// ===========================================================================
__device__ __forceinline__ uint32_t f2tf32(float v) {
    uint32_t r;
    asm("cvt.rna.tf32.f32 %0, %1;" : "=r"(r) : "f"(v));
    return r;
}
__device__ __forceinline__ void mma_tf32(float c[4],
                                         uint32_t a0, uint32_t a1,
                                         uint32_t a2, uint32_t a3,
                                         uint32_t b0, uint32_t b1) {
    asm volatile(
        "mma.sync.aligned.m16n8k8.row.col.f32.tf32.tf32.f32 "
        "{%0,%1,%2,%3}, {%4,%5,%6,%7}, {%8,%9}, {%0,%1,%2,%3};"
        : "+f"(c[0]), "+f"(c[1]), "+f"(c[2]), "+f"(c[3])
        : "r"(a0), "r"(a1), "r"(a2), "r"(a3), "r"(b0), "r"(b1));
}
__device__ __forceinline__ uint32_t smem_u32(const void* p) {
    uint32_t a;
    asm("{ .reg .u64 t; cvta.to.shared.u64 t, %1; cvt.u32.u64 %0, t; }"
        : "=r"(a) : "l"(p));
    return a;
}
__device__ __forceinline__ void cp_async16(uint32_t dst, const void* src) {
    asm volatile("cp.async.cg.shared.global [%0], [%1], 16;"
                 :: "r"(dst), "l"(src));
}
#define CP_COMMIT() asm volatile("cp.async.commit_group;" ::: "memory")
#define CP_WAIT1()  asm volatile("cp.async.wait_group 1;" ::: "memory")

// ===========================================================================
// Pipelined tf32 GEMM body:
//   C[.. x Nc] = (A[.. x 256] @ W[256 x Nc] + bias) (* rowscale)
// W must be tf32-pre-rounded (exact under HW truncation).
// 3-stage cp.async pipeline, 1 sync per K=16 chunk, 256 threads, warp 32x64.
// ===========================================================================
__device__ void tf32_gemm_v2(
    char* dyn, int bx, int by,
    const float* __restrict__ A, const float* __restrict__ W,
    const float* __restrict__ bias, const float* __restrict__ rowscale,
    float* __restrict__ C, int Nc)
{
    const int tid  = threadIdx.x;
    const int wid  = tid >> 5;
    const int lane = tid & 31;
    const int m0   = (wid & 3) * 32;
    const int n0   = (wid >> 2) * 64;
    const int grp  = lane >> 2;
    const int q    = lane & 3;
    const int bm   = by * 128;
    const int bn   = bx * 128;

    const uint32_t sbase = smem_u32(dyn);

    float c[2][8][4];
    #pragma unroll
    for (int i = 0; i < 2; i++)
        #pragma unroll
        for (int j = 0; j < 8; j++)
            #pragma unroll
            for (int e = 0; e < 4; e++) c[i][j][e] = 0.f;

    // issue one chunk's cp.asyncs into stage s
    auto issue = [&](int ck, int s) {
        uint32_t As = sbase + s * STAGE_BYTES;
        uint32_t Bs = As + A_STAGE_BYTES;
        const int k0 = ck * 16;
        #pragma unroll
        for (int i = 0; i < 2; i++) {
            int idx = tid * 2 + i;                 // 0..511
            int row = idx >> 2, k4 = (idx & 3) << 2;
            cp_async16(As + (uint32_t)(row * 80 + k4 * 4),
                       &A[(size_t)(bm + row) * 256 + k0 + k4]);
        }
        #pragma unroll
        for (int i = 0; i < 2; i++) {
            int idx = tid * 2 + i;
            int kr = idx >> 5, nc = (idx & 31) << 2;
            cp_async16(Bs + (uint32_t)(kr * 544 + nc * 4),
                       &W[(size_t)(k0 + kr) * Nc + bn + nc]);
        }
    };

    issue(0, 0); CP_COMMIT();
    issue(1, 1); CP_COMMIT();

    for (int ck = 0; ck < 16; ck++) {
        CP_WAIT1();
        __syncthreads();

        if (ck + 2 < 16) issue(ck + 2, (ck + 2) % 3);
        CP_COMMIT();                                  // empty groups in tail

        const int s = ck % 3;
        const float*    Am = (const float*)(dyn + s * STAGE_BYTES);       // [m][20]
        const uint32_t* Bk = (const uint32_t*)(dyn + s * STAGE_BYTES + A_STAGE_BYTES); // [k][136]

        #pragma unroll
        for (int ks = 0; ks < 16; ks += 8) {
            uint32_t a[2][4];
            #pragma unroll
            for (int mf = 0; mf < 2; mf++) {
                int mr = m0 + mf * 16 + grp;
                a[mf][0] = f2tf32(Am[mr * 20 + ks + q]);
                a[mf][1] = f2tf32(Am[(mr + 8) * 20 + ks + q]);
                a[mf][2] = f2tf32(Am[mr * 20 + ks + q + 4]);
                a[mf][3] = f2tf32(Am[(mr + 8) * 20 + ks + q + 4]);
            }
            uint32_t b[8][2];
            #pragma unroll
            for (int nf = 0; nf < 8; nf++) {
                int nb = n0 + nf * 8 + grp;
                b[nf][0] = Bk[(ks + q) * 136 + nb];
                b[nf][1] = Bk[(ks + q + 4) * 136 + nb];
            }
            #pragma unroll
            for (int mf = 0; mf < 2; mf++)
                #pragma unroll
                for (int nf = 0; nf < 8; nf++)
                    mma_tf32(c[mf][nf], a[mf][0], a[mf][1], a[mf][2], a[mf][3],
                             b[nf][0], b[nf][1]);
        }
        __syncthreads();
    }

    #pragma unroll
    for (int mf = 0; mf < 2; mf++) {
        int r0 = bm + m0 + mf * 16 + grp;
        int r1 = r0 + 8;
        float rs0 = rowscale ? rowscale[r0] : 1.f;
        float rs1 = rowscale ? rowscale[r1] : 1.f;
        #pragma unroll
        for (int nf = 0; nf < 8; nf++) {
            int col = bn + n0 + nf * 8 + 2 * q;
            float2 bv = *(const float2*)&bias[col];
            float2 lo = make_float2((c[mf][nf][0] + bv.x) * rs0,
                                    (c[mf][nf][1] + bv.y) * rs0);
            float2 hi = make_float2((c[mf][nf][2] + bv.x) * rs1,
                                    (c[mf][nf][3] + bv.y) * rs1);
            *(float2*)&C[(size_t)r0 * Nc + col] = lo;
            *(float2*)&C[(size_t)r1 * Nc + col] = hi;
        }
    }
}

// ===========================================================================
// f32x2 packed helpers
// ===========================================================================
__device__ __forceinline__ unsigned long long pack_dup(float v) {
    unsigned long long r;
    asm("mov.b64 %0, {%1, %1};" : "=l"(r) : "f"(v));
    return r;
}
__device__ __forceinline__ unsigned long long pack2(float lo, float hi) {
    unsigned long long r;
    asm("mov.b64 %0, {%1, %2};" : "=l"(r) : "f"(lo), "f"(hi));
    return r;
}
__device__ __forceinline__ float2 unpack2(unsigned long long v) {
    float2 r;
    asm("mov.b64 {%0, %1}, %2;" : "=f"(r.x), "=f"(r.y) : "l"(v));
    return r;
}
__device__ __forceinline__ void ffma2(unsigned long long& acc,
                                      unsigned long long a,
                                      unsigned long long b) {
    asm("fma.rn.f32x2 %0, %1, %2, %0;" : "+l"(acc) : "l"(a), "l"(b));
}

// ===========================================================================
// Exact fp32 SGEMM body (logits/deltas). Static smem (12.3KB, separate).
// ===========================================================================
__device__ void sgemm_body(
    int bx, int by,
    const float* __restrict__ A, const float* __restrict__ B,
    const float* __restrict__ bias, float* __restrict__ C, int Nc)
{
    __shared__ float Asf[16][128];
    __shared__ float Bsf[16][64];

    const int bm  = by * 128;
    const int bn  = bx * 64;
    const int tid = threadIdx.x;
    const int tr  = tid >> 4;
    const int tc  = tid & 15;

    unsigned long long acc2[4][4];
    #pragma unroll
    for (int i = 0; i < 4; i++)
        #pragma unroll
        for (int j = 0; j < 4; j++) acc2[i][j] = 0ULL;

    for (int k0 = 0; k0 < 256; k0 += 16) {
        #pragma unroll
        for (int i = 0; i < 2; i++) {
            int idx = tid * 2 + i;
            int row = idx >> 2;
            int c4  = (idx & 3) << 2;
            float4 v = *(const float4*)&A[(size_t)(bm + row) * 256 + k0 + c4];
            Asf[c4 + 0][row] = v.x;
            Asf[c4 + 1][row] = v.y;
            Asf[c4 + 2][row] = v.z;
            Asf[c4 + 3][row] = v.w;
        }
        {
            int row = tid >> 4;
            int c4  = (tid & 15) << 2;
            *(float4*)&Bsf[row][c4] =
                *(const float4*)&B[(size_t)(k0 + row) * Nc + bn + c4];
        }
        __syncthreads();

        #pragma unroll
        for (int k = 0; k < 16; k++) {
            unsigned long long aa[4], bb[4];
            #pragma unroll
            for (int i = 0; i < 4; i++) {
                float2 ap = *(const float2*)&Asf[k][tr * 8 + i * 2];
                aa[i] = pack2(ap.x, ap.y);
            }
            #pragma unroll
            for (int j = 0; j < 4; j++)
                bb[j] = pack_dup(Bsf[k][tc * 4 + j]);
            #pragma unroll
            for (int i = 0; i < 4; i++)
                #pragma unroll
                for (int j = 0; j < 4; j++)
                    ffma2(acc2[i][j], aa[i], bb[j]);
        }
        __syncthreads();
    }

    const int colb = bn + tc * 4;
    float4 bv = *(const float4*)&bias[colb];
    #pragma unroll
    for (int i = 0; i < 4; i++) {
        int row0 = bm + tr * 8 + i * 2;
        float2 c0 = unpack2(acc2[i][0]);
        float2 c1 = unpack2(acc2[i][1]);
        float2 c2 = unpack2(acc2[i][2]);
        float2 c3 = unpack2(acc2[i][3]);
        float4 lo = make_float4(c0.x + bv.x, c1.x + bv.y, c2.x + bv.z, c3.x + bv.w);
        float4 hi = make_float4(c0.y + bv.x, c1.y + bv.y, c2.y + bv.z, c3.y + bv.w);
        *(float4*)&C[(size_t)row0 * Nc + colb]       = lo;
        *(float4*)&C[(size_t)(row0 + 1) * Nc + colb] = hi;
    }
}

// ===========================================================================
// Weight pre-rounding (tf32 RNA) — makes B-path exact under HW truncation
// ===========================================================================
__global__ void __launch_bounds__(256) roundW_kernel(
    const float* __restrict__ W_val, const float* __restrict__ W_out)
{
    int i = blockIdx.x * 256 + threadIdx.x;          // 65536 threads
    g_Wval_r[i] = __uint_as_float(f2tf32(W_val[i]));
    g_Wout_r[i] = __uint_as_float(f2tf32(W_out[i]));
}

// ===========================================================================
// Fused phase-1: heterogeneous CTAs
// ===========================================================================
__global__ void __launch_bounds__(256, 2) phase1_kernel(
    const float* __restrict__ value,   const float* __restrict__ b_val,
    const float* __restrict__ vmaskin, const float* __restrict__ queries,
    const float* __restrict__ W_attn,  const float* __restrict__ b_attn,
    const float* __restrict__ W_off,   const float* __restrict__ b_off)
{
    extern __shared__ char dyn[];
    int sid = (int)(((long long)blockIdx.x * 997) % N_TOT);
    if (sid < N_VM) {
        tf32_gemm_v2(dyn, sid & 1, sid >> 1, value, g_Wval_r, b_val, vmaskin,
                     g_vmask, 256);
    } else if (sid < N_VM + N_LG) {
        int t = sid - N_VM;
        sgemm_body(t & 1, t >> 1, queries, W_attn, b_attn, g_logits, 128);
    } else {
        int t = sid - N_VM - N_LG;
        sgemm_body(t & 3, t >> 2, queries, W_off, b_off, g_deltas, 256);
    }
}

// ===========================================================================
// Output projection: pipelined tf32 GEMM
// ===========================================================================
__global__ void __launch_bounds__(256, 2) outproj_kernel(
    const float* __restrict__ bias, float* __restrict__ out)
{
    extern __shared__ char dyn[];
    tf32_gemm_v2(dyn, blockIdx.x, blockIdx.y, g_mdv, g_Wout_r, bias, nullptr,
                 out, 256);
}

// ===========================================================================
// Sampling (R7 version: LDG.128 per point, corner butterfly merge)
// ===========================================================================
__global__ void __launch_bounds__(256) sample_kernel(
    const float* __restrict__ geom)
{
    __shared__ int4   sI[8][16];
    __shared__ float4 sW[8][16];

    const int nq = blockIdx.x;
    const int n  = nq / SQ;
    const int t  = threadIdx.x;

    if (t < 128) {
        const int m = t >> 4;
        const int p = t & 15;

        float cx = 1.f / (1.f + __expf(-geom[nq * 4 + 0]));
        float cy = 1.f / (1.f + __expf(-geom[nq * 4 + 1]));
        float sw = 0.125f / (1.f + __expf(-geom[nq * 4 + 2]));
        float sh = 0.125f / (1.f + __expf(-geom[nq * 4 + 3]));

        float l = g_logits[(size_t)nq * 128 + m * 16 + p];
        float mx = l;
        #pragma unroll
        for (int d = 8; d >= 1; d >>= 1)
            mx = fmaxf(mx, __shfl_xor_sync(0xffffffffu, mx, d, 16));
        float e = __expf(l - mx);
        float s = e;
        #pragma unroll
        for (int d = 8; d >= 1; d >>= 1)
            s += __shfl_xor_sync(0xffffffffu, s, d, 16);
        const float a = e / s;

        const float dx = g_deltas[(size_t)nq * 256 + m * 32 + 2 * p];
        const float dy = g_deltas[(size_t)nq * 256 + m * 32 + 2 * p + 1];

        const int li = p >> 2;
        const int HW = 128 >> li;
        const int starts[4] = {0, 16384, 20480, 21504};
        const int start = starts[li];

        float px = fmaf(dx, sw, cx);
        float py = fmaf(dy, sh, cy);
        float gx = fminf(fmaxf(2.f * px - 1.f, -1.f), 1.f);
        float gy = fminf(fmaxf(2.f * py - 1.f, -1.f), 1.f);
        float x = (gx + 1.f) * (HW * 0.5f) - 0.5f;
        float y = (gy + 1.f) * (HW * 0.5f) - 0.5f;
        float x0f = floorf(x), y0f = floorf(y);
        float wx = x - x0f, wy = y - y0f;
        int x0 = (int)x0f, y0 = (int)y0f;
        int x1 = x0 + 1,  y1 = y0 + 1;

        bool vx0 = (x0 >= 0) & (x0 < HW);
        bool vx1 = (x1 >= 0) & (x1 < HW);
        bool vy0 = (y0 >= 0) & (y0 < HW);
        bool vy1 = (y1 >= 0) & (y1 < HW);

        int4 idx;
        float4 w;
        idx.x = (vx0 & vy0) ? (start + y0 * HW + x0) * 256 : 0;
        idx.y = (vx1 & vy0) ? (start + y0 * HW + x1) * 256 : 0;
        idx.z = (vx0 & vy1) ? (start + y1 * HW + x0) * 256 : 0;
        idx.w = (vx1 & vy1) ? (start + y1 * HW + x1) * 256 : 0;
        w.x = (vx0 & vy0) ? a * (1.f - wx) * (1.f - wy) : 0.f;
        w.y = (vx1 & vy0) ? a * wx * (1.f - wy)         : 0.f;
        w.z = (vx0 & vy1) ? a * (1.f - wx) * wy         : 0.f;
        w.w = (vx1 & vy1) ? a * wx * wy                 : 0.f;

        sI[m][p] = idx;
        sW[m][p] = w;
    }
    __syncthreads();

    const int m      = t >> 5;
    const int lane   = t & 31;
    const int corner = lane >> 3;
    const int cb     = lane & 7;
    const float* __restrict__ vb4 =
        g_vmask + (size_t)n * S_TOT * 256 + m * 32 + cb * 4;
    const int*   __restrict__ pI = (const int*)&sI[m][0]   + corner;
    const float* __restrict__ pW = (const float*)&sW[m][0] + corner;

    float4 acc = make_float4(0.f, 0.f, 0.f, 0.f);
    #pragma unroll
    for (int p = 0; p < 16; p++) {
        int   I = pI[4 * p];
        float w = pW[4 * p];
        float4 v = *(const float4*)(vb4 + I);
        acc.x = fmaf(w, v.x, acc.x);
        acc.y = fmaf(w, v.y, acc.y);
        acc.z = fmaf(w, v.z, acc.z);
        acc.w = fmaf(w, v.w, acc.w);
    }

    #pragma unroll
    for (int d = 8; d <= 16; d <<= 1) {
        acc.x += __shfl_xor_sync(0xffffffffu, acc.x, d);
        acc.y += __shfl_xor_sync(0xffffffffu, acc.y, d);
        acc.z += __shfl_xor_sync(0xffffffffu, acc.z, d);
        acc.w += __shfl_xor_sync(0xffffffffu, acc.w, d);
    }
    if (lane < 8)
        *(float4*)&g_mdv[(size_t)nq * 256 + m * 32 + cb * 4] = acc;
}

// ===========================================================================
// Launch
// ===========================================================================
extern "C" void kernel_launch(void* const* d_in, const int* in_sizes, int n_in,
                              void* d_out, int out_size)
{
    const float* queries = (const float*)d_in[0];
    const float* geom    = (const float*)d_in[1];
    const float* value   = (const float*)d_in[2];
    const float* vmaskin = (const float*)d_in[3];
    const float* W_off   = (const float*)d_in[4];
    const float* b_off   = (const float*)d_in[5];
    const float* W_attn  = (const float*)d_in[6];
    const float* b_attn  = (const float*)d_in[7];
    const float* b_val   = (const float*)d_in[9];
    const float* W_val   = (const float*)d_in[8];
    const float* W_out   = (const float*)d_in[10];
    const float* b_out   = (const float*)d_in[11];
    float* out = (float*)d_out;

    static int attr_done = 0;
    if (!attr_done) {
        cudaFuncSetAttribute(phase1_kernel,
                             cudaFuncAttributeMaxDynamicSharedMemorySize,
                             TF32_DSMEM);
        cudaFuncSetAttribute(outproj_kernel,
                             cudaFuncAttributeMaxDynamicSharedMemorySize,
                             TF32_DSMEM);
        attr_done = 1;
    }

    // Pre-round weights (tf32 RNA) for the tensor-core B path
    roundW_kernel<<<256, 256>>>(W_val, W_out);
    // Phase 1 (concurrent): vmask tf32-MMA + logits/deltas exact fp32
    phase1_kernel<<<N_TOT, 256, TF32_DSMEM>>>(value, b_val, vmaskin,
                                              queries, W_attn, b_attn,
                                              W_off, b_off);
    // Phase 2: sampling -> g_mdv
    sample_kernel<<<NQ, 256>>>(geom);
    // Phase 3: out = mdv @ W_out + b_out (tf32 MMA, pipelined)
    outproj_kernel<<<dim3(2, NQ / 128), 256, TF32_DSMEM>>>(b_out, out);
}